// round 5
// baseline (speedup 1.0000x reference)
#include <cuda_runtime.h>

#define BB   4
#define HH   256
#define WW   256
#define CC   64
#define CIN  3
#define OFFC 18
#define OFFP 20
#define NP   16

// Scratch (allocation-free)
__device__ float4 g_feat[NP * BB * HH * WW];       // NC4HW4 features
__device__ float  g_off [BB * HH * WW * OFFC];     // NHWC offsets
__device__ float  g_cwT [CIN * 9 * CC];
__device__ float  g_owT [CC * 9 * OFFP];
__device__ float  g_dwT [9 * CC * CC];             // [k][c][o]

typedef unsigned long long ull;

__device__ __forceinline__ ull pack2(float lo, float hi) {
    ull r; asm("mov.b64 %0, {%1,%2};" : "=l"(r) : "f"(lo), "f"(hi)); return r;
}
__device__ __forceinline__ float2 unpack2(ull v) {
    float2 r; asm("mov.b64 {%0,%1}, %2;" : "=f"(r.x), "=f"(r.y) : "l"(v)); return r;
}
#define FMA2(a, x, y) asm("fma.rn.f32x2 %0, %1, %2, %0;" : "+l"(a) : "l"(x), "l"(y))

// ---------------------------------------------------------------------------
__global__ void prep_kernel(const float* __restrict__ cw,
                            const float* __restrict__ ow,
                            const float* __restrict__ dw) {
    int t = blockIdx.x * blockDim.x + threadIdx.x;
    int nt = gridDim.x * blockDim.x;
    for (int idx = t; idx < CIN * 9 * CC; idx += nt) {
        int o = idx % CC, r = idx / CC;
        g_cwT[idx] = cw[o * (CIN * 9) + r];
    }
    for (int idx = t; idx < CC * 9 * OFFP; idx += nt) {
        int oc = idx % OFFP, ct = idx / OFFP;
        g_owT[idx] = (oc < OFFC) ? ow[oc * (CC * 9) + ct] : 0.0f;
    }
    for (int idx = t; idx < 9 * CC * CC; idx += nt) {
        int o = idx % CC, c = (idx / CC) % CC, k = idx / (CC * CC);
        g_dwT[idx] = dw[(o * CC + c) * 9 + k];
    }
}

// ---------------------------------------------------------------------------
// Kernel 1: x NCHW -> feat NC4HW4, 3x3 conv pad 1
// ---------------------------------------------------------------------------
__global__ void __launch_bounds__(256) conv_in_kernel(const float* __restrict__ x,
                                                      const float* __restrict__ cb) {
    __shared__ __align__(16) float sw[CIN * 9 * CC];
    __shared__ float sb[CC];
    for (int idx = threadIdx.x; idx < CIN * 9 * CC; idx += 256) sw[idx] = g_cwT[idx];
    if (threadIdx.x < CC) sb[threadIdx.x] = cb[threadIdx.x];
    __syncthreads();

    const int b = blockIdx.x / HH, h = blockIdx.x % HH, w = threadIdx.x;

    ull acc[32];
    #pragma unroll
    for (int q = 0; q < 32; q++) acc[q] = pack2(sb[2 * q], sb[2 * q + 1]);

    #pragma unroll 1
    for (int ci = 0; ci < CIN; ci++) {
        #pragma unroll
        for (int i = 0; i < 3; i++) {
            int y = h - 1 + i;
            bool yv = ((unsigned)y < HH);
            #pragma unroll
            for (int j = 0; j < 3; j++) {
                int xx = w - 1 + j;
                float v = (yv && (unsigned)xx < WW) ? x[((b * CIN + ci) * HH + y) * WW + xx] : 0.0f;
                ull s2 = pack2(v, v);
                const ulonglong2* wp = (const ulonglong2*)&sw[(ci * 9 + i * 3 + j) * CC];
                #pragma unroll
                for (int q = 0; q < 16; q++) {
                    ulonglong2 ww = wp[q];
                    FMA2(acc[2 * q], s2, ww.x);
                    FMA2(acc[2 * q + 1], s2, ww.y);
                }
            }
        }
    }

    const int ppix = h * WW + w;
    #pragma unroll
    for (int q4 = 0; q4 < NP; q4++) {
        float2 lo = unpack2(acc[2 * q4]);
        float2 hi = unpack2(acc[2 * q4 + 1]);
        g_feat[(q4 * BB + b) * HH * WW + ppix] = make_float4(lo.x, lo.y, hi.x, hi.y);
    }
}

// ---------------------------------------------------------------------------
// Kernel 2: feat NC4HW4 -> offsets NHWC(18), 2 rows per block
// ---------------------------------------------------------------------------
__global__ void __launch_bounds__(256) conv_off_kernel(const float* __restrict__ ob) {
    __shared__ __align__(16) float sw[CC * 9 * OFFP];
    for (int idx = threadIdx.x; idx < CC * 9 * OFFP; idx += 256) sw[idx] = g_owT[idx];
    __syncthreads();

    const int b = blockIdx.x / (HH / 2);
    const int h0 = (blockIdx.x % (HH / 2)) * 2;
    const int w = threadIdx.x;

    ull accA[9], accB[9];
    #pragma unroll
    for (int q = 0; q < 9; q++) {
        ull t = pack2(ob[2 * q], ob[2 * q + 1]);
        accA[q] = t; accB[q] = t;
    }

    #pragma unroll 1
    for (int i = 0; i < 3; i++) {
        int yA = h0 - 1 + i, yB = h0 + i;
        bool yAv = ((unsigned)yA < HH), yBv = ((unsigned)yB < HH);
        #pragma unroll 1
        for (int j = 0; j < 3; j++) {
            int xx = w - 1 + j;
            bool xv = ((unsigned)xx < WW);
            bool vA = yAv && xv, vB = yBv && xv;
            int xc = xv ? xx : 0;
            int iA = (vA ? yA : 0) * WW + xc;
            int iB = (vB ? yB : 0) * WW + xc;
            const int tap = i * 3 + j;
            #pragma unroll 1
            for (int c4 = 0; c4 < NP; c4++) {
                const float4* pc = g_feat + (c4 * BB + b) * HH * WW;
                float4 fa = vA ? pc[iA] : make_float4(0.f, 0.f, 0.f, 0.f);
                float4 fb = vB ? pc[iB] : make_float4(0.f, 0.f, 0.f, 0.f);
                const float fav[4] = {fa.x, fa.y, fa.z, fa.w};
                const float fbv[4] = {fb.x, fb.y, fb.z, fb.w};
                #pragma unroll
                for (int cc = 0; cc < 4; cc++) {
                    ull sa = pack2(fav[cc], fav[cc]);
                    ull sb2 = pack2(fbv[cc], fbv[cc]);
                    const float* wrow = &sw[((c4 * 4 + cc) * 9 + tap) * OFFP];
                    const ulonglong2* wp = (const ulonglong2*)wrow;
                    #pragma unroll
                    for (int q2 = 0; q2 < 4; q2++) {
                        ulonglong2 ww = wp[q2];
                        FMA2(accA[2 * q2], sa, ww.x);
                        FMA2(accA[2 * q2 + 1], sa, ww.y);
                        FMA2(accB[2 * q2], sb2, ww.x);
                        FMA2(accB[2 * q2 + 1], sb2, ww.y);
                    }
                    ull w8 = *(const ull*)(wrow + 16);
                    FMA2(accA[8], sa, w8);
                    FMA2(accB[8], sb2, w8);
                }
            }
        }
    }

    float* opA = &g_off[((b * HH + h0) * WW + w) * OFFC];
    float* opB = opA + WW * OFFC;
    #pragma unroll
    for (int q = 0; q < 9; q++) {
        ((float2*)opA)[q] = unpack2(accA[q]);
        ((float2*)opB)[q] = unpack2(accB[q]);
    }
}

// ---------------------------------------------------------------------------
// Kernel 3: deform conv as staged GEMM, square 32px x 32o warp tiles.
// Block = 256 threads, 128 pixels. Per tap: gather+bilinear into S[64][128]
// (double buffered), stream W tap tile (16KB, double buffered), register tile
// 4px x 8o per thread with only 128B distinct S + 128B distinct W per c/warp.
// ---------------------------------------------------------------------------
__device__ __forceinline__ void tap_coords(int h, int w_img, int kk,
                                           const float* off,
                                           float& w00, float& w01, float& w10, float& w11,
                                           int& i00, int& i01, int& i10, int& i11) {
    const int i = kk / 3, j = kk - 3 * i;
    float sy = (float)(h - 1 + i) + off[2 * kk];
    float sx = (float)(w_img - 1 + j) + off[2 * kk + 1];
    float y0f = floorf(sy), x0f = floorf(sx);
    float dy = sy - y0f, dx = sx - x0f;
    int y0 = (int)y0f, x0 = (int)x0f, y1 = y0 + 1, x1 = x0 + 1;
    bool vy0 = ((unsigned)y0 < HH), vy1 = ((unsigned)y1 < HH);
    bool vx0 = ((unsigned)x0 < WW), vx1 = ((unsigned)x1 < WW);
    w00 = (1.f - dy) * (1.f - dx) * ((vy0 && vx0) ? 1.f : 0.f);
    w01 = (1.f - dy) * dx         * ((vy0 && vx1) ? 1.f : 0.f);
    w10 = dy * (1.f - dx)         * ((vy1 && vx0) ? 1.f : 0.f);
    w11 = dy * dx                 * ((vy1 && vx1) ? 1.f : 0.f);
    int y0c = min(max(y0, 0), HH - 1), y1c = min(max(y1, 0), HH - 1);
    int x0c = min(max(x0, 0), WW - 1), x1c = min(max(x1, 0), WW - 1);
    i00 = y0c * WW + x0c; i01 = y0c * WW + x1c;
    i10 = y1c * WW + x0c; i11 = y1c * WW + x1c;
}

__global__ void __launch_bounds__(256, 2) deform_kernel(const float* __restrict__ db,
                                                        float* __restrict__ out) {
    extern __shared__ __align__(16) float smem[];
    float* Sb0 = smem;            // 8192 floats (S[64][128])
    float* Sb1 = smem + 8192;
    float* Wb0 = smem + 16384;    // 4096 floats (W[64][64])
    float* Wb1 = smem + 20480;

    const int tid = threadIdx.x;
    const int bi = blockIdx.x;
    const int b = bi >> 9;
    const int rest = bi & 511;
    const int h = rest >> 1;
    const int wbase = (rest & 1) << 7;

    // gather mapping
    const int px_g = tid & 127;
    const int pg_half = tid >> 7;
    const int w_img = wbase + px_g;

    // GEMM mapping: square 32px x 32o warp tiles
    const int lane = tid & 31;
    const int warp = tid >> 5;
    const int pxg = warp & 3;     // 4 px-groups of 32
    const int og  = warp >> 2;    // 2 o-groups of 32
    const int pxl = lane >> 2;    // 8 sub-tiles of 4 px
    const int ol  = lane & 3;     // 4 sub-tiles of 8 o
    const int sOff = pxg * 32 + pxl * 4;
    const int wOff = og * 32 + ol * 8;

    float off[18];
    {
        const float2* op2 = (const float2*)(g_off + (((b * HH + h) * WW) + w_img) * OFFC);
        #pragma unroll
        for (int q = 0; q < 9; q++) { float2 t2 = op2[q]; off[2 * q] = t2.x; off[2 * q + 1] = t2.y; }
    }

    const float4* gW = (const float4*)g_dwT;

    // Prologue: W(0) + gather tap 0 into buffer 0
    #pragma unroll
    for (int q = 0; q < 4; q++)
        ((float4*)Wb0)[q * 256 + tid] = gW[q * 256 + tid];
    {
        float w00, w01, w10, w11; int i00, i01, i10, i11;
        tap_coords(h, w_img, 0, off, w00, w01, w10, w11, i00, i01, i10, i11);
        #pragma unroll
        for (int p = 0; p < 8; p++) {
            const int pl = pg_half * 8 + p;
            const float4* pc = g_feat + (pl * BB + b) * HH * WW;
            float4 c00 = pc[i00], c01 = pc[i01], c10 = pc[i10], c11 = pc[i11];
            float s0 = w00 * c00.x + w01 * c01.x + w10 * c10.x + w11 * c11.x;
            float s1 = w00 * c00.y + w01 * c01.y + w10 * c10.y + w11 * c11.y;
            float s2 = w00 * c00.z + w01 * c01.z + w10 * c10.z + w11 * c11.z;
            float s3 = w00 * c00.w + w01 * c01.w + w10 * c10.w + w11 * c11.w;
            const int cb = pl * 4;
            Sb0[(cb + 0) * 128 + px_g] = s0;
            Sb0[(cb + 1) * 128 + px_g] = s1;
            Sb0[(cb + 2) * 128 + px_g] = s2;
            Sb0[(cb + 3) * 128 + px_g] = s3;
        }
    }
    __syncthreads();

    ull acc[4][4];
    #pragma unroll
    for (int pp = 0; pp < 4; pp++)
        #pragma unroll
        for (int op = 0; op < 4; op++) acc[pp][op] = 0ull;

    #pragma unroll 1
    for (int k = 0; k < 9; k++) {
        const float* Sb = (k & 1) ? Sb1 : Sb0;
        const float* Wb = (k & 1) ? Wb1 : Wb0;
        float* Sd = (k & 1) ? Sb0 : Sb1;
        float4* Wd = (float4*)((k & 1) ? Wb0 : Wb1);
        const int kk = k + 1;
        const bool dog = (kk < 9);

        float w00 = 0.f, w01 = 0.f, w10 = 0.f, w11 = 0.f;
        int i00 = 0, i01 = 0, i10 = 0, i11 = 0;
        if (dog) tap_coords(h, w_img, kk, off, w00, w01, w10, w11, i00, i01, i10, i11);
        const float4* gWk = gW + kk * 1024;

        #pragma unroll
        for (int p = 0; p < 8; p++) {
            float4 c00, c01, c10, c11, wt;
            if (dog) {
                const int pl = pg_half * 8 + p;
                const float4* pc = g_feat + (pl * BB + b) * HH * WW;
                c00 = pc[i00]; c01 = pc[i01]; c10 = pc[i10]; c11 = pc[i11];
                if (p < 4) wt = gWk[p * 256 + tid];
            }

            // GEMM chunk: c = p*8 .. p*8+7
            #pragma unroll
            for (int cc = 0; cc < 8; cc++) {
                const int c = p * 8 + cc;
                float4 sv = *(const float4*)(Sb + c * 128 + sOff);
                const ulonglong2* wrow = (const ulonglong2*)(Wb + c * 64 + wOff);
                ulonglong2 wA = wrow[0];
                ulonglong2 wB = wrow[1];
                ull s;
                s = pack2(sv.x, sv.x);
                FMA2(acc[0][0], s, wA.x); FMA2(acc[0][1], s, wA.y);
                FMA2(acc[0][2], s, wB.x); FMA2(acc[0][3], s, wB.y);
                s = pack2(sv.y, sv.y);
                FMA2(acc[1][0], s, wA.x); FMA2(acc[1][1], s, wA.y);
                FMA2(acc[1][2], s, wB.x); FMA2(acc[1][3], s, wB.y);
                s = pack2(sv.z, sv.z);
                FMA2(acc[2][0], s, wA.x); FMA2(acc[2][1], s, wA.y);
                FMA2(acc[2][2], s, wB.x); FMA2(acc[2][3], s, wB.y);
                s = pack2(sv.w, sv.w);
                FMA2(acc[3][0], s, wA.x); FMA2(acc[3][1], s, wA.y);
                FMA2(acc[3][2], s, wB.x); FMA2(acc[3][3], s, wB.y);
            }

            if (dog) {
                float s0 = w00 * c00.x + w01 * c01.x + w10 * c10.x + w11 * c11.x;
                float s1 = w00 * c00.y + w01 * c01.y + w10 * c10.y + w11 * c11.y;
                float s2 = w00 * c00.z + w01 * c01.z + w10 * c10.z + w11 * c11.z;
                float s3 = w00 * c00.w + w01 * c01.w + w10 * c10.w + w11 * c11.w;
                const int cb = (pg_half * 8 + p) * 4;
                Sd[(cb + 0) * 128 + px_g] = s0;
                Sd[(cb + 1) * 128 + px_g] = s1;
                Sd[(cb + 2) * 128 + px_g] = s2;
                Sd[(cb + 3) * 128 + px_g] = s3;
                if (p < 4) Wd[p * 256 + tid] = wt;
            }
        }
        __syncthreads();
    }

    // Epilogue: add bias, write NCHW
    const float2* db2 = (const float2*)db;
    #pragma unroll
    for (int op = 0; op < 4; op++) {
        float2 bz = db2[wOff / 2 + op];
        const int o = wOff + op * 2;
        #pragma unroll
        for (int pp = 0; pp < 4; pp++) {
            float2 v = unpack2(acc[pp][op]);
            const int base = ((b * CC + o) * HH + h) * WW + wbase + sOff + pp;
            out[base] = v.x + bz.x;
            out[base + HH * WW] = v.y + bz.y;
        }
    }
}

// ---------------------------------------------------------------------------
extern "C" void kernel_launch(void* const* d_in, const int* in_sizes, int n_in,
                              void* d_out, int out_size) {
    const float* x        = (const float*)d_in[0];
    const float* conv_w   = (const float*)d_in[1];
    const float* conv_b   = (const float*)d_in[2];
    const float* offset_w = (const float*)d_in[3];
    const float* offset_b = (const float*)d_in[4];
    const float* deform_w = (const float*)d_in[5];
    const float* deform_b = (const float*)d_in[6];
    float* out = (float*)d_out;

    const int dsm = 24576 * (int)sizeof(float);   // 96KB
    cudaFuncSetAttribute(deform_kernel, cudaFuncAttributeMaxDynamicSharedMemorySize, dsm);

    prep_kernel<<<96, 512>>>(conv_w, offset_w, deform_w);
    conv_in_kernel<<<BB * HH, 256>>>(x, conv_b);
    conv_off_kernel<<<BB * HH / 2, 256>>>(offset_b);
    deform_kernel<<<BB * HH * 2, 256, dsm>>>(deform_b, out);
}

// round 6
// speedup vs baseline: 1.1648x; 1.1648x over previous
#include <cuda_runtime.h>

#define BB   4
#define HH   256
#define WW   256
#define CC   64
#define CIN  3
#define OFFC 18
#define OFFP 20
#define NP   16

// Scratch (allocation-free)
__device__ float4 g_feat[NP * BB * HH * WW];       // NC4HW4 features
__device__ float  g_off [BB * HH * WW * OFFC];     // NHWC offsets
__device__ float  g_cwT [CIN * 9 * CC];
__device__ float  g_owT [CC * 9 * OFFP];
__device__ float  g_dwT [9 * CC * CC];             // [k][c][o]

typedef unsigned long long ull;

__device__ __forceinline__ ull pack2(float lo, float hi) {
    ull r; asm("mov.b64 %0, {%1,%2};" : "=l"(r) : "f"(lo), "f"(hi)); return r;
}
__device__ __forceinline__ float2 unpack2(ull v) {
    float2 r; asm("mov.b64 {%0,%1}, %2;" : "=f"(r.x), "=f"(r.y) : "l"(v)); return r;
}
#define FMA2(a, x, y) asm("fma.rn.f32x2 %0, %1, %2, %0;" : "+l"(a) : "l"(x), "l"(y))

// ---------------------------------------------------------------------------
__global__ void prep_kernel(const float* __restrict__ cw,
                            const float* __restrict__ ow,
                            const float* __restrict__ dw) {
    int t = blockIdx.x * blockDim.x + threadIdx.x;
    int nt = gridDim.x * blockDim.x;
    for (int idx = t; idx < CIN * 9 * CC; idx += nt) {
        int o = idx % CC, r = idx / CC;
        g_cwT[idx] = cw[o * (CIN * 9) + r];
    }
    for (int idx = t; idx < CC * 9 * OFFP; idx += nt) {
        int oc = idx % OFFP, ct = idx / OFFP;
        g_owT[idx] = (oc < OFFC) ? ow[oc * (CC * 9) + ct] : 0.0f;
    }
    for (int idx = t; idx < 9 * CC * CC; idx += nt) {
        int o = idx % CC, c = (idx / CC) % CC, k = idx / (CC * CC);
        g_dwT[idx] = dw[(o * CC + c) * 9 + k];
    }
}

// ---------------------------------------------------------------------------
// Kernel 1: x NCHW -> feat NC4HW4, 3x3 conv pad 1
// ---------------------------------------------------------------------------
__global__ void __launch_bounds__(256) conv_in_kernel(const float* __restrict__ x,
                                                      const float* __restrict__ cb) {
    __shared__ __align__(16) float sw[CIN * 9 * CC];
    __shared__ float sb[CC];
    for (int idx = threadIdx.x; idx < CIN * 9 * CC; idx += 256) sw[idx] = g_cwT[idx];
    if (threadIdx.x < CC) sb[threadIdx.x] = cb[threadIdx.x];
    __syncthreads();

    const int b = blockIdx.x / HH, h = blockIdx.x % HH, w = threadIdx.x;

    ull acc[32];
    #pragma unroll
    for (int q = 0; q < 32; q++) acc[q] = pack2(sb[2 * q], sb[2 * q + 1]);

    #pragma unroll 1
    for (int ci = 0; ci < CIN; ci++) {
        #pragma unroll
        for (int i = 0; i < 3; i++) {
            int y = h - 1 + i;
            bool yv = ((unsigned)y < HH);
            #pragma unroll
            for (int j = 0; j < 3; j++) {
                int xx = w - 1 + j;
                float v = (yv && (unsigned)xx < WW) ? x[((b * CIN + ci) * HH + y) * WW + xx] : 0.0f;
                ull s2 = pack2(v, v);
                const ulonglong2* wp = (const ulonglong2*)&sw[(ci * 9 + i * 3 + j) * CC];
                #pragma unroll
                for (int q = 0; q < 16; q++) {
                    ulonglong2 ww = wp[q];
                    FMA2(acc[2 * q], s2, ww.x);
                    FMA2(acc[2 * q + 1], s2, ww.y);
                }
            }
        }
    }

    const int ppix = h * WW + w;
    #pragma unroll
    for (int q4 = 0; q4 < NP; q4++) {
        float2 lo = unpack2(acc[2 * q4]);
        float2 hi = unpack2(acc[2 * q4 + 1]);
        g_feat[(q4 * BB + b) * HH * WW + ppix] = make_float4(lo.x, lo.y, hi.x, hi.y);
    }
}

// ---------------------------------------------------------------------------
// Kernel 2: feat NC4HW4 -> offsets NHWC(18), 2 rows per block
// ---------------------------------------------------------------------------
__global__ void __launch_bounds__(256) conv_off_kernel(const float* __restrict__ ob) {
    __shared__ __align__(16) float sw[CC * 9 * OFFP];
    for (int idx = threadIdx.x; idx < CC * 9 * OFFP; idx += 256) sw[idx] = g_owT[idx];
    __syncthreads();

    const int b = blockIdx.x / (HH / 2);
    const int h0 = (blockIdx.x % (HH / 2)) * 2;
    const int w = threadIdx.x;

    ull accA[9], accB[9];
    #pragma unroll
    for (int q = 0; q < 9; q++) {
        ull t = pack2(ob[2 * q], ob[2 * q + 1]);
        accA[q] = t; accB[q] = t;
    }

    #pragma unroll 1
    for (int i = 0; i < 3; i++) {
        int yA = h0 - 1 + i, yB = h0 + i;
        bool yAv = ((unsigned)yA < HH), yBv = ((unsigned)yB < HH);
        #pragma unroll 1
        for (int j = 0; j < 3; j++) {
            int xx = w - 1 + j;
            bool xv = ((unsigned)xx < WW);
            bool vA = yAv && xv, vB = yBv && xv;
            int xc = xv ? xx : 0;
            int iA = (vA ? yA : 0) * WW + xc;
            int iB = (vB ? yB : 0) * WW + xc;
            const int tap = i * 3 + j;
            #pragma unroll 1
            for (int c4 = 0; c4 < NP; c4++) {
                const float4* pc = g_feat + (c4 * BB + b) * HH * WW;
                float4 fa = vA ? pc[iA] : make_float4(0.f, 0.f, 0.f, 0.f);
                float4 fb = vB ? pc[iB] : make_float4(0.f, 0.f, 0.f, 0.f);
                const float fav[4] = {fa.x, fa.y, fa.z, fa.w};
                const float fbv[4] = {fb.x, fb.y, fb.z, fb.w};
                #pragma unroll
                for (int cc = 0; cc < 4; cc++) {
                    ull sa = pack2(fav[cc], fav[cc]);
                    ull sb2 = pack2(fbv[cc], fbv[cc]);
                    const float* wrow = &sw[((c4 * 4 + cc) * 9 + tap) * OFFP];
                    const ulonglong2* wp = (const ulonglong2*)wrow;
                    #pragma unroll
                    for (int q2 = 0; q2 < 4; q2++) {
                        ulonglong2 ww = wp[q2];
                        FMA2(accA[2 * q2], sa, ww.x);
                        FMA2(accA[2 * q2 + 1], sa, ww.y);
                        FMA2(accB[2 * q2], sb2, ww.x);
                        FMA2(accB[2 * q2 + 1], sb2, ww.y);
                    }
                    ull w8 = *(const ull*)(wrow + 16);
                    FMA2(accA[8], sa, w8);
                    FMA2(accB[8], sb2, w8);
                }
            }
        }
    }

    float* opA = &g_off[((b * HH + h0) * WW + w) * OFFC];
    float* opB = opA + WW * OFFC;
    #pragma unroll
    for (int q = 0; q < 9; q++) {
        ((float2*)opA)[q] = unpack2(accA[q]);
        ((float2*)opB)[q] = unpack2(accB[q]);
    }
}

// ---------------------------------------------------------------------------
// Kernel 3: deform conv as staged GEMM. 128 threads, 4 warps.
// Warp tile = 128px x 16o (lane = 4 contiguous px, 32 ull accumulators).
// Per tap: gather+bilinear into S[64][128] (double buffered), stream W tap
// tile (16KB double buffered). S read 4wf clean, W broadcast 4wf per c.
// ---------------------------------------------------------------------------
__device__ __forceinline__ void tap_coords(int h, int w_img, int kk,
                                           const float* off,
                                           float& w00, float& w01, float& w10, float& w11,
                                           int& i00, int& i01, int& i10, int& i11) {
    const int i = kk / 3, j = kk - 3 * i;
    float sy = (float)(h - 1 + i) + off[2 * kk];
    float sx = (float)(w_img - 1 + j) + off[2 * kk + 1];
    float y0f = floorf(sy), x0f = floorf(sx);
    float dy = sy - y0f, dx = sx - x0f;
    int y0 = (int)y0f, x0 = (int)x0f, y1 = y0 + 1, x1 = x0 + 1;
    bool vy0 = ((unsigned)y0 < HH), vy1 = ((unsigned)y1 < HH);
    bool vx0 = ((unsigned)x0 < WW), vx1 = ((unsigned)x1 < WW);
    w00 = (1.f - dy) * (1.f - dx) * ((vy0 && vx0) ? 1.f : 0.f);
    w01 = (1.f - dy) * dx         * ((vy0 && vx1) ? 1.f : 0.f);
    w10 = dy * (1.f - dx)         * ((vy1 && vx0) ? 1.f : 0.f);
    w11 = dy * dx                 * ((vy1 && vx1) ? 1.f : 0.f);
    int y0c = min(max(y0, 0), HH - 1), y1c = min(max(y1, 0), HH - 1);
    int x0c = min(max(x0, 0), WW - 1), x1c = min(max(x1, 0), WW - 1);
    i00 = y0c * WW + x0c; i01 = y0c * WW + x1c;
    i10 = y1c * WW + x0c; i11 = y1c * WW + x1c;
}

__global__ void __launch_bounds__(128, 2) deform_kernel(const float* __restrict__ db,
                                                        float* __restrict__ out) {
    extern __shared__ __align__(16) float smem[];
    float* Sb0 = smem;            // 8192 floats (S[64][128])
    float* Sb1 = smem + 8192;
    float* Wb0 = smem + 16384;    // 4096 floats (W[64][64])
    float* Wb1 = smem + 20480;

    const int tid = threadIdx.x;
    const int bi = blockIdx.x;
    const int b = bi >> 9;
    const int rest = bi & 511;
    const int h = rest >> 1;
    const int wbase = (rest & 1) << 7;

    const int px_g = tid;                 // gather pixel (0..127)
    const int w_img = wbase + px_g;

    // GEMM mapping: warp -> 16 outputs, lane -> 4 contiguous pixels
    const int lane = tid & 31;
    const int o_t = tid >> 5;             // 0..3
    const int wOff = o_t * 16;

    float off[18];
    {
        const float2* op2 = (const float2*)(g_off + (((b * HH + h) * WW) + w_img) * OFFC);
        #pragma unroll
        for (int q = 0; q < 9; q++) { float2 t2 = op2[q]; off[2 * q] = t2.x; off[2 * q + 1] = t2.y; }
    }

    const float4* gW = (const float4*)g_dwT;

    // Prologue: load W(0) (1024 float4 / 128 threads = 8 each) + gather tap 0
    #pragma unroll
    for (int q = 0; q < 8; q++)
        ((float4*)Wb0)[q * 128 + tid] = gW[q * 128 + tid];
    {
        float w00, w01, w10, w11; int i00, i01, i10, i11;
        tap_coords(h, w_img, 0, off, w00, w01, w10, w11, i00, i01, i10, i11);
        #pragma unroll
        for (int pl = 0; pl < NP; pl++) {
            const float4* pc = g_feat + (pl * BB + b) * HH * WW;
            float4 c00 = pc[i00], c01 = pc[i01], c10 = pc[i10], c11 = pc[i11];
            float s0 = w00 * c00.x + w01 * c01.x + w10 * c10.x + w11 * c11.x;
            float s1 = w00 * c00.y + w01 * c01.y + w10 * c10.y + w11 * c11.y;
            float s2 = w00 * c00.z + w01 * c01.z + w10 * c10.z + w11 * c11.z;
            float s3 = w00 * c00.w + w01 * c01.w + w10 * c10.w + w11 * c11.w;
            const int cb = pl * 4;
            Sb0[(cb + 0) * 128 + px_g] = s0;
            Sb0[(cb + 1) * 128 + px_g] = s1;
            Sb0[(cb + 2) * 128 + px_g] = s2;
            Sb0[(cb + 3) * 128 + px_g] = s3;
        }
    }
    __syncthreads();

    ull acc[4][8];
    #pragma unroll
    for (int pp = 0; pp < 4; pp++)
        #pragma unroll
        for (int op = 0; op < 8; op++) acc[pp][op] = 0ull;

    #pragma unroll 1
    for (int k = 0; k < 9; k++) {
        const float* Sb = (k & 1) ? Sb1 : Sb0;
        const float* Wb = (k & 1) ? Wb1 : Wb0;
        float* Sd = (k & 1) ? Sb0 : Sb1;
        float4* Wd = (float4*)((k & 1) ? Wb0 : Wb1);
        const int kk = k + 1;
        const bool dog = (kk < 9);

        float w00 = 0.f, w01 = 0.f, w10 = 0.f, w11 = 0.f;
        int i00 = 0, i01 = 0, i10 = 0, i11 = 0;
        if (dog) tap_coords(h, w_img, kk, off, w00, w01, w10, w11, i00, i01, i10, i11);
        const float4* gWk = gW + kk * 1024;

        #pragma unroll
        for (int p = 0; p < NP; p++) {
            float4 c00, c01, c10, c11, wt;
            if (dog) {
                const float4* pc = g_feat + (p * BB + b) * HH * WW;
                c00 = pc[i00]; c01 = pc[i01]; c10 = pc[i10]; c11 = pc[i11];
                if (p < 8) wt = gWk[p * 128 + tid];
            }

            // GEMM chunk: c = p*4 .. p*4+3
            #pragma unroll
            for (int cc = 0; cc < 4; cc++) {
                const int c = p * 4 + cc;
                float4 sv = *(const float4*)(Sb + c * 128 + lane * 4);
                const ulonglong2* wrow = (const ulonglong2*)(Wb + c * 64 + wOff);
                ulonglong2 wA = wrow[0];
                ulonglong2 wB = wrow[1];
                ulonglong2 wC = wrow[2];
                ulonglong2 wD = wrow[3];
                ull s;
                s = pack2(sv.x, sv.x);
                FMA2(acc[0][0], s, wA.x); FMA2(acc[0][1], s, wA.y);
                FMA2(acc[0][2], s, wB.x); FMA2(acc[0][3], s, wB.y);
                FMA2(acc[0][4], s, wC.x); FMA2(acc[0][5], s, wC.y);
                FMA2(acc[0][6], s, wD.x); FMA2(acc[0][7], s, wD.y);
                s = pack2(sv.y, sv.y);
                FMA2(acc[1][0], s, wA.x); FMA2(acc[1][1], s, wA.y);
                FMA2(acc[1][2], s, wB.x); FMA2(acc[1][3], s, wB.y);
                FMA2(acc[1][4], s, wC.x); FMA2(acc[1][5], s, wC.y);
                FMA2(acc[1][6], s, wD.x); FMA2(acc[1][7], s, wD.y);
                s = pack2(sv.z, sv.z);
                FMA2(acc[2][0], s, wA.x); FMA2(acc[2][1], s, wA.y);
                FMA2(acc[2][2], s, wB.x); FMA2(acc[2][3], s, wB.y);
                FMA2(acc[2][4], s, wC.x); FMA2(acc[2][5], s, wC.y);
                FMA2(acc[2][6], s, wD.x); FMA2(acc[2][7], s, wD.y);
                s = pack2(sv.w, sv.w);
                FMA2(acc[3][0], s, wA.x); FMA2(acc[3][1], s, wA.y);
                FMA2(acc[3][2], s, wB.x); FMA2(acc[3][3], s, wB.y);
                FMA2(acc[3][4], s, wC.x); FMA2(acc[3][5], s, wC.y);
                FMA2(acc[3][6], s, wD.x); FMA2(acc[3][7], s, wD.y);
            }

            if (dog) {
                float s0 = w00 * c00.x + w01 * c01.x + w10 * c10.x + w11 * c11.x;
                float s1 = w00 * c00.y + w01 * c01.y + w10 * c10.y + w11 * c11.y;
                float s2 = w00 * c00.z + w01 * c01.z + w10 * c10.z + w11 * c11.z;
                float s3 = w00 * c00.w + w01 * c01.w + w10 * c10.w + w11 * c11.w;
                const int cb = p * 4;
                Sd[(cb + 0) * 128 + px_g] = s0;
                Sd[(cb + 1) * 128 + px_g] = s1;
                Sd[(cb + 2) * 128 + px_g] = s2;
                Sd[(cb + 3) * 128 + px_g] = s3;
                if (p < 8) Wd[p * 128 + tid] = wt;
            }
        }
        __syncthreads();
    }

    // Epilogue: add bias, write NCHW
    const float2* db2 = (const float2*)db;
    #pragma unroll
    for (int op = 0; op < 8; op++) {
        float2 bz = db2[o_t * 8 + op];
        const int o = wOff + op * 2;
        #pragma unroll
        for (int pp = 0; pp < 4; pp++) {
            float2 v = unpack2(acc[pp][op]);
            const int base = ((b * CC + o) * HH + h) * WW + wbase + lane * 4 + pp;
            out[base] = v.x + bz.x;
            out[base + HH * WW] = v.y + bz.y;
        }
    }
}

// ---------------------------------------------------------------------------
extern "C" void kernel_launch(void* const* d_in, const int* in_sizes, int n_in,
                              void* d_out, int out_size) {
    const float* x        = (const float*)d_in[0];
    const float* conv_w   = (const float*)d_in[1];
    const float* conv_b   = (const float*)d_in[2];
    const float* offset_w = (const float*)d_in[3];
    const float* offset_b = (const float*)d_in[4];
    const float* deform_w = (const float*)d_in[5];
    const float* deform_b = (const float*)d_in[6];
    float* out = (float*)d_out;

    const int dsm = 24576 * (int)sizeof(float);   // 96KB
    cudaFuncSetAttribute(deform_kernel, cudaFuncAttributeMaxDynamicSharedMemorySize, dsm);

    prep_kernel<<<96, 512>>>(conv_w, offset_w, deform_w);
    conv_in_kernel<<<BB * HH, 256>>>(x, conv_b);
    conv_off_kernel<<<BB * HH / 2, 256>>>(offset_b);
    deform_kernel<<<BB * HH * 2, 128, dsm>>>(deform_b, out);
}